// round 6
// baseline (speedup 1.0000x reference)
#include <cuda_runtime.h>
#include <cuda_bf16.h>

#define POOL 7
#define NCELL 49
#define C 256

// 128 threads: 64 channel-lanes (float4 x 64 = C) x 2 cell-groups.
// Small blocks => all 2000 blocks co-resident (single wave, no tail).
__global__ __launch_bounds__(128, 14) void roi_align_kernel(
    const float* __restrict__ boxes,
    const float* __restrict__ meta,
    const float* __restrict__ f2,
    const float* __restrict__ f3,
    const float* __restrict__ f4,
    const float* __restrict__ f5,
    float* __restrict__ out,
    int N)
{
    const int box_id = blockIdx.x;         // 0 .. B*N-1
    const int batch  = box_id / N;
    const int tid    = threadIdx.x;

    __shared__ int4   s_off[NCELL];
    __shared__ float2 s_frac[NCELL];       // {fx, fy}

    // --- per-box scalars (redundant per thread; cheap) ---
    const float by1 = boxes[box_id * 4 + 0];
    const float bx1 = boxes[box_id * 4 + 1];
    const float by2 = boxes[box_id * 4 + 2];
    const float bx2 = boxes[box_id * 4 + 3];

    const float area = meta[4] * meta[5];
    const float lvl  = log2f(sqrtf((by2 - by1) * (bx2 - bx1)) / (224.0f / sqrtf(area)));
    float lv = 4.0f + rintf(lvl);          // rintf = round-half-even = jnp.round
    lv = fminf(fmaxf(lv, 2.0f), 5.0f);
    const int level = (int)lv;

    int Hs;
    const float* f;
    if (level == 2)      { Hs = 256; f = f2; }
    else if (level == 3) { Hs = 128; f = f3; }
    else if (level == 4) { Hs = 64;  f = f4; }
    else                 { Hs = 32;  f = f5; }
    const int Ws = Hs;
    const float* base = f + (size_t)batch * Hs * Ws * C;

    // --- build the 49 cell descriptors (one thread per cell) ---
    if (tid < NCELL) {
        const int py = tid / POOL;
        const int px = tid - py * POOL;

        const float ys = by1 * (float)(Hs - 1)
                       + (float)py * ((by2 - by1) * (float)(Hs - 1) / (float)(POOL - 1));
        const float xs = bx1 * (float)(Ws - 1)
                       + (float)px * ((bx2 - bx1) * (float)(Ws - 1) / (float)(POOL - 1));

        const float y0f = floorf(ys);
        const float x0f = floorf(xs);
        int y0 = min(max((int)y0f, 0), Hs - 1);
        int x0 = min(max((int)x0f, 0), Ws - 1);
        const int y1 = min(y0 + 1, Hs - 1);
        const int x1 = min(x0 + 1, Ws - 1);

        s_off[tid]  = make_int4((y0 * Ws + x0) * C, (y0 * Ws + x1) * C,
                                (y1 * Ws + x0) * C, (y1 * Ws + x1) * C);
        s_frac[tid] = make_float2(xs - x0f, ys - y0f);
    }
    __syncthreads();

    // --- main loop: group g covers cells g, g+2, g+4, ... ---
    const int ch = (tid & 63) * 4;         // channel offset
    const int g  = tid >> 6;               // cell group 0..1
    const float* bch   = base + ch;
    float*       obase = out + (size_t)box_id * (NCELL * C) + ch;

    auto do_cell = [&](int cell) {
        const int4   off = s_off[cell];
        const float2 fr  = s_frac[cell];

        const float4 tl = *(const float4*)(bch + off.x);
        const float4 tr = *(const float4*)(bch + off.y);
        const float4 bl = *(const float4*)(bch + off.z);
        const float4 br = *(const float4*)(bch + off.w);

        float4 o;
        {
            const float top = tl.x + (tr.x - tl.x) * fr.x;
            const float bot = bl.x + (br.x - bl.x) * fr.x;
            o.x = top + (bot - top) * fr.y;
        }
        {
            const float top = tl.y + (tr.y - tl.y) * fr.x;
            const float bot = bl.y + (br.y - bl.y) * fr.x;
            o.y = top + (bot - top) * fr.y;
        }
        {
            const float top = tl.z + (tr.z - tl.z) * fr.x;
            const float bot = bl.z + (br.z - bl.z) * fr.x;
            o.z = top + (bot - top) * fr.y;
        }
        {
            const float top = tl.w + (tr.w - tl.w) * fr.x;
            const float bot = bl.w + (br.w - bl.w) * fr.x;
            o.w = top + (bot - top) * fr.y;
        }
        __stwt((float4*)(obase + (size_t)cell * C), o);  // streaming store
    };

    // k = 0..11: cells g+4k and g+4k+2 (group 0: 0..46 even; group 1: 1..47 odd)
    #pragma unroll 1
    for (int k = 0; k < 12; k++) {
        const int c0 = g + 4 * k;
        do_cell(c0);
        do_cell(c0 + 2);
    }
    if (g == 0) do_cell(48);
}

extern "C" void kernel_launch(void* const* d_in, const int* in_sizes, int n_in,
                              void* d_out, int out_size) {
    const float* boxes = (const float*)d_in[0];
    const float* meta  = (const float*)d_in[1];
    const float* f2    = (const float*)d_in[2];
    const float* f3    = (const float*)d_in[3];
    const float* f4    = (const float*)d_in[4];
    const float* f5    = (const float*)d_in[5];
    float* out = (float*)d_out;

    const int BN = in_sizes[0] / 4;                    // total boxes = B*N
    const int B  = in_sizes[2] / (256 * 256 * 256);    // feat2 = B*256*256*C
    const int N  = BN / B;

    roi_align_kernel<<<BN, 128>>>(boxes, meta, f2, f3, f4, f5, out, N);
}

// round 7
// speedup vs baseline: 1.0347x; 1.0347x over previous
#include <cuda_runtime.h>
#include <cuda_bf16.h>

#define POOL 7
#define NCELL 49
#define C 256

// 2 boxes per 256-thread block: warps 0-3 -> box 2*bid, warps 4-7 -> box 2*bid+1.
// 1000 blocks < 148 SMs * 8 resident (32 regs) => single fully-resident wave, no tail.
__global__ __launch_bounds__(256, 8) void roi_align_kernel(
    const float* __restrict__ boxes,
    const float* __restrict__ meta,
    const float* __restrict__ f2,
    const float* __restrict__ f3,
    const float* __restrict__ f4,
    const float* __restrict__ f5,
    float* __restrict__ out,
    int N, int BN)
{
    const int tid  = threadIdx.x;
    const int half = tid >> 7;             // 0 or 1: which box this thread works on
    const int htid = tid & 127;            // thread id within the half

    const int box_id = blockIdx.x * 2 + half;
    const bool active = (box_id < BN);

    // Packed per-cell descriptor: {off_top | (dx_flag<<31), off_bot, fx_bits, fy_bits}
    __shared__ int4 s_desc[2][NCELL];

    int   Hs = 32;
    const float* base = f5;
    float by1 = 0.f, bx1 = 0.f, by2 = 0.f, bx2 = 0.f;

    if (active) {
        by1 = boxes[box_id * 4 + 0];
        bx1 = boxes[box_id * 4 + 1];
        by2 = boxes[box_id * 4 + 2];
        bx2 = boxes[box_id * 4 + 3];

        const float area = meta[4] * meta[5];
        const float lvl  = log2f(sqrtf((by2 - by1) * (bx2 - bx1)) / (224.0f / sqrtf(area)));
        float lv = 4.0f + rintf(lvl);      // rintf = round-half-even = jnp.round
        lv = fminf(fmaxf(lv, 2.0f), 5.0f);
        const int level = (int)lv;

        const float* f;
        if (level == 2)      { Hs = 256; f = f2; }
        else if (level == 3) { Hs = 128; f = f3; }
        else if (level == 4) { Hs = 64;  f = f4; }
        else                 { Hs = 32;  f = f5; }

        const int batch = box_id / N;
        base = f + (size_t)batch * Hs * Hs * C;
    }

    // --- build the 49 cell descriptors (one thread per cell, per half) ---
    if (active && htid < NCELL) {
        const int Ws = Hs;
        const int py = htid / POOL;
        const int px = htid - py * POOL;

        const float ys = by1 * (float)(Hs - 1)
                       + (float)py * ((by2 - by1) * (float)(Hs - 1) / (float)(POOL - 1));
        const float xs = bx1 * (float)(Ws - 1)
                       + (float)px * ((bx2 - bx1) * (float)(Ws - 1) / (float)(POOL - 1));

        const float y0f = floorf(ys);
        const float x0f = floorf(xs);
        int y0 = min(max((int)y0f, 0), Hs - 1);
        int x0 = min(max((int)x0f, 0), Ws - 1);
        const int y1 = min(y0 + 1, Hs - 1);
        const int x1 = min(x0 + 1, Ws - 1);

        const int off_top = (y0 * Ws + x0) * C;         // element offset of tl
        const int off_bot = (y1 * Ws + x0) * C;         // element offset of bl
        const int dxflag  = (x1 != x0) ? (int)0x80000000 : 0;  // tr = tl + C if set

        s_desc[half][htid] = make_int4(off_top | dxflag, off_bot,
                                       __float_as_int(xs - x0f),
                                       __float_as_int(ys - y0f));
    }
    __syncthreads();

    if (!active) return;

    // --- main loop: 64 lanes x float4 = C channels; 2 cell-groups per half ---
    const int ch = (htid & 63) * 4;        // channel offset
    const int g  = htid >> 6;              // cell group 0..1
    const float* bch   = base + ch;
    float*       obase = out + (size_t)box_id * (NCELL * C) + ch;

    // group 0: even cells 0..48 (25), group 1: odd cells 1..47 (24)
    #pragma unroll 2
    for (int cell = g; cell < NCELL; cell += 2) {
        const int4 d = s_desc[half][cell];
        const int off_top = d.x & 0x7fffffff;
        const int off_bot = d.y;
        const int dx      = (d.x < 0) ? C : 0;          // x-step in elements
        const float fx    = __int_as_float(d.z);
        const float fy    = __int_as_float(d.w);

        const float4 tl = *(const float4*)(bch + off_top);
        const float4 tr = *(const float4*)(bch + off_top + dx);
        const float4 bl = *(const float4*)(bch + off_bot);
        const float4 br = *(const float4*)(bch + off_bot + dx);

        float4 o;
        {
            const float top = tl.x + (tr.x - tl.x) * fx;
            const float bot = bl.x + (br.x - bl.x) * fx;
            o.x = top + (bot - top) * fy;
        }
        {
            const float top = tl.y + (tr.y - tl.y) * fx;
            const float bot = bl.y + (br.y - bl.y) * fx;
            o.y = top + (bot - top) * fy;
        }
        {
            const float top = tl.z + (tr.z - tl.z) * fx;
            const float bot = bl.z + (br.z - bl.z) * fx;
            o.z = top + (bot - top) * fy;
        }
        {
            const float top = tl.w + (tr.w - tl.w) * fx;
            const float bot = bl.w + (br.w - bl.w) * fx;
            o.w = top + (bot - top) * fy;
        }
        __stwt((float4*)(obase + (size_t)cell * C), o);  // streaming store
    }
}

extern "C" void kernel_launch(void* const* d_in, const int* in_sizes, int n_in,
                              void* d_out, int out_size) {
    const float* boxes = (const float*)d_in[0];
    const float* meta  = (const float*)d_in[1];
    const float* f2    = (const float*)d_in[2];
    const float* f3    = (const float*)d_in[3];
    const float* f4    = (const float*)d_in[4];
    const float* f5    = (const float*)d_in[5];
    float* out = (float*)d_out;

    const int BN = in_sizes[0] / 4;                    // total boxes = B*N
    const int B  = in_sizes[2] / (256 * 256 * 256);    // feat2 = B*256*256*C
    const int N  = BN / B;

    const int nblocks = (BN + 1) / 2;
    roi_align_kernel<<<nblocks, 256>>>(boxes, meta, f2, f3, f4, f5, out, N, BN);
}

// round 8
// speedup vs baseline: 1.1101x; 1.0728x over previous
#include <cuda_runtime.h>
#include <cuda_bf16.h>

#define POOL 7
#define NCELL 49
#define C 256

__global__ __launch_bounds__(256) void roi_align_kernel(
    const float* __restrict__ boxes,
    const float* __restrict__ meta,
    const float* __restrict__ f2,
    const float* __restrict__ f3,
    const float* __restrict__ f4,
    const float* __restrict__ f5,
    float* __restrict__ out,
    int N)
{
    const int box_id = blockIdx.x;         // 0 .. B*N-1
    const int batch  = box_id / N;
    const int tid    = threadIdx.x;

    // Per-cell descriptors: packed element offsets of the 4 corners + frac weights
    __shared__ int4   s_off[NCELL];
    __shared__ float2 s_frac[NCELL];       // {fx, fy}

    // --- per-box scalars (redundant per thread; cheap) ---
    const float by1 = boxes[box_id * 4 + 0];
    const float bx1 = boxes[box_id * 4 + 1];
    const float by2 = boxes[box_id * 4 + 2];
    const float bx2 = boxes[box_id * 4 + 3];

    const float area = meta[4] * meta[5];
    const float lvl  = log2f(sqrtf((by2 - by1) * (bx2 - bx1)) / (224.0f / sqrtf(area)));
    float lv = 4.0f + rintf(lvl);          // rintf = round-half-even = jnp.round
    lv = fminf(fmaxf(lv, 2.0f), 5.0f);
    const int level = (int)lv;

    int Hs;
    const float* f;
    if (level == 2)      { Hs = 256; f = f2; }
    else if (level == 3) { Hs = 128; f = f3; }
    else if (level == 4) { Hs = 64;  f = f4; }
    else                 { Hs = 32;  f = f5; }
    const int Ws = Hs;
    const float* base = f + (size_t)batch * Hs * Ws * C;

    // --- build the 49 cell descriptors (one thread per cell) ---
    if (tid < NCELL) {
        const int py = tid / POOL;
        const int px = tid - py * POOL;

        const float ys = by1 * (float)(Hs - 1)
                       + (float)py * ((by2 - by1) * (float)(Hs - 1) / (float)(POOL - 1));
        const float xs = bx1 * (float)(Ws - 1)
                       + (float)px * ((bx2 - bx1) * (float)(Ws - 1) / (float)(POOL - 1));

        const float y0f = floorf(ys);
        const float x0f = floorf(xs);
        int y0 = min(max((int)y0f, 0), Hs - 1);
        int x0 = min(max((int)x0f, 0), Ws - 1);
        const int y1 = min(y0 + 1, Hs - 1);
        const int x1 = min(x0 + 1, Ws - 1);

        s_off[tid]  = make_int4((y0 * Ws + x0) * C, (y0 * Ws + x1) * C,
                                (y1 * Ws + x0) * C, (y1 * Ws + x1) * C);
        s_frac[tid] = make_float2(xs - x0f, ys - y0f);
    }
    __syncthreads();

    // --- main loop: 64 lanes x float4 cover C=256; 4 cell-groups ---
    const int ch = (tid & 63) * 4;         // channel offset
    const int g  = tid >> 6;               // cell group 0..3
    const float* bch   = base + ch;
    float*       obase = out + (size_t)box_id * (NCELL * C) + ch;

    auto do_cell = [&](int cell) {
        const int4   off = s_off[cell];
        const float2 fr  = s_frac[cell];

        // L2-only loads: reads never hit L1 (working set >> L1), so bypass the
        // L1 allocate/fill path and its outstanding-miss tracking entirely.
        const float4 tl = __ldcg((const float4*)(bch + off.x));
        const float4 tr = __ldcg((const float4*)(bch + off.y));
        const float4 bl = __ldcg((const float4*)(bch + off.z));
        const float4 br = __ldcg((const float4*)(bch + off.w));

        float4 o;
        {
            const float top = tl.x + (tr.x - tl.x) * fr.x;
            const float bot = bl.x + (br.x - bl.x) * fr.x;
            o.x = top + (bot - top) * fr.y;
        }
        {
            const float top = tl.y + (tr.y - tl.y) * fr.x;
            const float bot = bl.y + (br.y - bl.y) * fr.x;
            o.y = top + (bot - top) * fr.y;
        }
        {
            const float top = tl.z + (tr.z - tl.z) * fr.x;
            const float bot = bl.z + (br.z - bl.z) * fr.x;
            o.z = top + (bot - top) * fr.y;
        }
        {
            const float top = tl.w + (tr.w - tl.w) * fr.x;
            const float bot = bl.w + (br.w - bl.w) * fr.x;
            o.w = top + (bot - top) * fr.y;
        }
        __stwt((float4*)(obase + (size_t)cell * C), o);  // streaming: keep L2 for reads
    };

    // groups 0..3 cover cells g+4k; two independent cells per iteration
    #pragma unroll 1
    for (int k = 0; k < 6; k++) {
        const int c0 = g + 8 * k;
        do_cell(c0);
        do_cell(c0 + 4);
    }
    if (g == 0) do_cell(48);
}

extern "C" void kernel_launch(void* const* d_in, const int* in_sizes, int n_in,
                              void* d_out, int out_size) {
    const float* boxes = (const float*)d_in[0];
    const float* meta  = (const float*)d_in[1];
    const float* f2    = (const float*)d_in[2];
    const float* f3    = (const float*)d_in[3];
    const float* f4    = (const float*)d_in[4];
    const float* f5    = (const float*)d_in[5];
    float* out = (float*)d_out;

    const int BN = in_sizes[0] / 4;                    // total boxes = B*N
    const int B  = in_sizes[2] / (256 * 256 * 256);    // feat2 = B*256*256*C
    const int N  = BN / B;

    roi_align_kernel<<<BN, 256>>>(boxes, meta, f2, f3, f4, f5, out, N);
}